// round 1
// baseline (speedup 1.0000x reference)
#include <cuda_runtime.h>

// y[b,t,c*S+s] = x[b,t,c] * w[c*S+s]
// B=512, T=128, C=128, S=32, OUT_DIM=4096
// Pure HBM-write-bound broadcast multiply. One float4 of output per thread.

#define C_DIM    128
#define OUT_DIM  4096
#define S_DIM    32

__global__ __launch_bounds__(256, 8)
void csi_embedding_kernel(const float* __restrict__ x,
                          const float4* __restrict__ w4,
                          float4* __restrict__ out4,
                          int n4)   // total float4s in output
{
    int idx4 = blockIdx.x * blockDim.x + threadIdx.x;
    if (idx4 >= n4) return;

    // 4096 floats per row = 1024 float4 per row
    int row    = idx4 >> 10;          // / 1024
    int within = idx4 & 1023;         // float4 index within row
    int c      = within >> 3;         // 32 floats (= 8 float4) per channel

    float xs = __ldg(&x[row * C_DIM + c]);      // broadcast across 8 threads
    float4 wv = __ldg(&w4[within]);             // 16 KiB table, L1-resident

    float4 r;
    r.x = xs * wv.x;
    r.y = xs * wv.y;
    r.z = xs * wv.z;
    r.w = xs * wv.w;
    out4[idx4] = r;
}

extern "C" void kernel_launch(void* const* d_in, const int* in_sizes, int n_in,
                              void* d_out, int out_size)
{
    const float*  x  = (const float*)d_in[0];
    const float4* w4 = (const float4*)d_in[1];
    float4* out4 = (float4*)d_out;

    int n4 = out_size / 4;                 // 67,108,864 float4s
    int threads = 256;
    int blocks = (n4 + threads - 1) / threads;
    csi_embedding_kernel<<<blocks, threads>>>(x, w4, out4, n4);
}

// round 2
// speedup vs baseline: 1.4496x; 1.4496x over previous
#include <cuda_runtime.h>

// y[b,t,c*S+s] = x[b,t,c] * w[c*S+s]
// B=512, T=128, C=128, S=32, OUT_DIM=4096. Output = 1 GiB fp32, write-bound.
//
// Strategy: each block produces 2 complete output rows (2*4096 floats = 2048
// float4s). x (256 floats) and w (16 KiB) are staged in shared memory with one
// cooperative load + one barrier, so the 8-deep unrolled store loop has NO
// dependent global loads — pure LDS -> FMUL -> STG.128 streaming.

#define ROWS_PER_BLOCK 2
#define THREADS        256
#define F4_PER_BLOCK   (ROWS_PER_BLOCK * 1024)   // 2048 float4s
#define ITERS          (F4_PER_BLOCK / THREADS)  // 8

__global__ __launch_bounds__(THREADS, 8)
void csi_embedding_kernel(const float*  __restrict__ x,
                          const float4* __restrict__ w4,
                          float4*       __restrict__ out4)
{
    __shared__ float4 s_w[1024];                 // 16 KiB: full w table
    __shared__ float  s_x[ROWS_PER_BLOCK * 128]; // 1 KiB: x for 2 rows

    const int tid = threadIdx.x;

    // Stage w: 256 threads x 4 float4, coalesced (L1-hit after first block/SM)
    #pragma unroll
    for (int k = 0; k < 4; k++)
        s_w[k * THREADS + tid] = __ldg(&w4[k * THREADS + tid]);

    // Stage x: 256 consecutive floats = rows [2*bid, 2*bid+1], coalesced
    s_x[tid] = __ldg(&x[blockIdx.x * (ROWS_PER_BLOCK * 128) + tid]);

    __syncthreads();

    const long long base = (long long)blockIdx.x * F4_PER_BLOCK;

    #pragma unroll
    for (int k = 0; k < ITERS; k++) {
        int pos = k * THREADS + tid;             // 0..2047 within block
        // 1024 float4 per row; 8 float4 per channel
        float  xs = s_x[pos >> 3];               // (row_local*128 + c), broadcast x8
        float4 wv = s_w[pos & 1023];

        float4 r;
        r.x = xs * wv.x;
        r.y = xs * wv.y;
        r.z = xs * wv.z;
        r.w = xs * wv.w;
        __stcs(&out4[base + pos], r);            // streaming store, skip L2 retention
    }
}

extern "C" void kernel_launch(void* const* d_in, const int* in_sizes, int n_in,
                              void* d_out, int out_size)
{
    const float*  x  = (const float*)d_in[0];
    const float4* w4 = (const float4*)d_in[1];
    float4* out4 = (float4*)d_out;

    // out_size = 512*128*4096 floats -> /4 float4s -> /2048 per block = 32768 blocks
    int blocks = (out_size / 4) / F4_PER_BLOCK;
    csi_embedding_kernel<<<blocks, THREADS>>>(x, w4, out4);
}